// round 2
// baseline (speedup 1.0000x reference)
#include <cuda_runtime.h>

#define BB 256
#define SS 1024
#define DD 64
#define HD 128
#define FF 40
#define TS 16
#define NTILE (SS / TS)

typedef unsigned long long u64;

// ---------- f32x2 helpers (FFMA2 only reachable via PTX) ----------
__device__ __forceinline__ u64 pk2(float x, float y) {
    u64 r;
    asm("mov.b64 %0, {%1, %2};" : "=l"(r) : "f"(x), "f"(y));
    return r;
}
__device__ __forceinline__ float2 upk2(u64 v) {
    float2 f;
    asm("mov.b64 {%0, %1}, %2;" : "=f"(f.x), "=f"(f.y) : "l"(v));
    return f;
}
__device__ __forceinline__ u64 sp2(float x) { return pk2(x, x); }
__device__ __forceinline__ void fma2(u64& acc, u64 a, u64 b) {
    asm("fma.rn.f32x2 %0, %1, %2, %0;" : "+l"(acc) : "l"(a), "l"(b));
}
__device__ __forceinline__ float prelu_f(float x, float a) {
    return x >= 0.0f ? x : a * x;
}

// ---------- scratch (device globals; no allocation allowed) ----------
__device__ float g_ytrans[BB * HD];                 // [B][128]
__device__ float g_weff[2u * BB * 2 * DD * FF];     // [br][b][h][64][40]
__device__ float g_c[2 * BB * 2 * FF];              // [br][b][h][40]

// ================= kernel 1: y_trans = l2norm(prelu(y @ w_ty + b_ty)) =====
__global__ void k_ytrans(const float* __restrict__ y,
                         const float* __restrict__ w,
                         const float* __restrict__ bias,
                         const float* __restrict__ a_) {
    int b = blockIdx.x;
    int j = threadIdx.x;  // 0..127
    float a = a_[0];
    __shared__ float ys[DD];
    __shared__ float red[4];
    if (j < DD) ys[j] = y[b * DD + j];
    __syncthreads();
    float acc = bias[j];
#pragma unroll
    for (int d = 0; d < DD; d++) acc = fmaf(ys[d], w[d * HD + j], acc);
    float t = prelu_f(acc, a);
    float sq = t * t;
#pragma unroll
    for (int off = 16; off; off >>= 1) sq += __shfl_xor_sync(~0u, sq, off);
    if ((j & 31) == 0) red[j >> 5] = sq;
    __syncthreads();
    float s = red[0] + red[1] + red[2] + red[3];
    float inv = 1.0f / fmaxf(sqrtf(s), 1e-12f);
    g_ytrans[b * HD + j] = t * inv;
}

// ================= kernel 2: W_eff and c per (b, h, branch) ===============
__global__ void k_weff(const float* __restrict__ lw1, const float* __restrict__ lb1,
                       const float* __restrict__ nw1, const float* __restrict__ nb1,
                       const float* __restrict__ uid, const float* __restrict__ osb,
                       const float* __restrict__ zip) {
    int b = blockIdx.x, h = blockIdx.y, br = blockIdx.z;
    const float* w1 = br ? nw1 : lw1;
    const float* b1 = br ? nb1 : lb1;
    __shared__ float yh[DD];
    __shared__ float side[56];
    int t = threadIdx.x;  // 256 threads
    if (t < 64) {
        yh[t] = g_ytrans[b * HD + h * DD + t];
    } else if (t < 120) {
        int k = t - 64;
        side[k] = (k < 32) ? uid[b * 32 + k]
                : (k < 40) ? osb[b * 8 + (k - 32)]
                           : zip[b * 16 + (k - 40)];
    }
    __syncthreads();
    float* wout = g_weff + (((size_t)br * BB + b) * 2 + h) * (DD * FF);
    for (int i = t; i < DD * FF; i += 256) {
        int d = i / FF, f = i - d * FF;
        wout[i] = w1[d * FF + f] + w1[(128 + d) * FF + f] + yh[d] * w1[(64 + d) * FF + f];
    }
    if (t < FF) {
        float acc = b1[t];
#pragma unroll 8
        for (int d = 0; d < DD; d++)
            acc += yh[d] * (w1[(192 + d) * FF + t] - w1[(128 + d) * FF + t]);
#pragma unroll 8
        for (int k = 0; k < 56; k++) acc += side[k] * w1[(256 + k) * FF + t];
        g_c[(((size_t)br * BB + b) * 2 + h) * FF + t] = acc;
    }
}

// ================= kernel 3: main fused kernel ============================
// smem layout (float offsets); all offsets multiple of 4 for vector access
#define OFF_W    0        // 8192  : w_x [64][128]
#define OFF_WEFF 8192     // 5120  : W_eff [2][64][40]
#define OFF_BX   13312    // 128   : b_x
#define OFF_XT   13440    // 1280  : xT [64][20] (stride 20)
#define OFF_XNT  14720    // 2560  : xnT [128][20]
#define OFF_H1   17280    // 1280  : h1 [16][2][40]
#define OFF_C    18560    // 80    : c [2][40]
#define OFF_W2   18640    // 40    : w2
#define OFF_P    18680    // 32    : p [16][2]
#define OFF_RED  18712    // 32    : [8 warps][4]
#define OFF_INV  18744    // 16
#define SM_FLOATS 18760
#define SM_BYTES (SM_FLOATS * 4 + 1024)  // +acc buffer
#define OFF_ACC  18760    // 256

__global__ __launch_bounds__(256, 2) void k_main(
    const float* __restrict__ xl, const float* __restrict__ xn,
    const float* __restrict__ wlx, const float* __restrict__ blx, const float* __restrict__ alx,
    const float* __restrict__ wnx, const float* __restrict__ bnx, const float* __restrict__ anx,
    const float* __restrict__ la1, const float* __restrict__ na1,
    const float* __restrict__ lw2, const float* __restrict__ lb2,
    const float* __restrict__ nw2, const float* __restrict__ nb2,
    float* __restrict__ out) {
    extern __shared__ float sm[];
    const int b = blockIdx.x;
    const int br = blockIdx.y;
    const int t = threadIdx.x;
    const int lane = t & 31, warp = t >> 5;

    const float* xg = br ? xn : xl;
    const float* wx = br ? wnx : wlx;
    const float* bx = br ? bnx : blx;
    const float ax = br ? anx[0] : alx[0];
    const float a1 = br ? na1[0] : la1[0];
    const float* w2g = br ? nw2 : lw2;
    const float b2 = br ? nb2[0] : lb2[0];

    float* w_s = sm + OFF_W;
    float* weff_s = sm + OFF_WEFF;
    float* bxs = sm + OFF_BX;
    float* xT = sm + OFF_XT;
    float* xnT = sm + OFF_XNT;
    float* h1_s = sm + OFF_H1;
    float* c_s = sm + OFF_C;
    float* w2_s = sm + OFF_W2;
    float* p_s = sm + OFF_P;
    float* red = sm + OFF_RED;
    float* inv_s = sm + OFF_INV;
    float* accb = sm + OFF_ACC;

    // ---- preload block-invariant weights ----
    {
        const float4* ws4 = (const float4*)wx;
        float4* wd4 = (float4*)w_s;
        for (int i = t; i < (DD * HD) / 4; i += 256) wd4[i] = ws4[i];
        const float* wesrc = g_weff + ((size_t)br * BB + b) * 2 * (DD * FF);
        const float4* we4 = (const float4*)wesrc;
        float4* wed4 = (float4*)weff_s;
        for (int i = t; i < (2 * DD * FF) / 4; i += 256) wed4[i] = we4[i];
        const float* csrc = g_c + ((size_t)br * BB + b) * 2 * FF;
        if (t < HD) bxs[t] = bx[t];
        else if (t < HD + 80) c_s[t - HD] = csrc[t - HD];
        else if (t < HD + 80 + FF) w2_s[t - HD - 80] = w2g[t - HD - 80];
    }
    __syncthreads();

    const int jp = t & 63;   // column pair index (cols 2jp, 2jp+1)
    const int rg = t >> 6;   // row group (rows rg*4 .. rg*4+3)
    float racc = 0.0f;       // persistent output accumulator

    for (int tile = 0; tile < NTILE; ++tile) {
        const int s0 = tile * TS;
        // ---- load x tile [16][64] transposed into xT[64][20] ----
#pragma unroll
        for (int it = 0; it < 4; ++it) {
            int e = t + it * 256;
            int r = e >> 6, d = e & 63;
            xT[d * 20 + r] = xg[((size_t)b * SS + s0 + r) * DD + d];
        }
        __syncthreads();

        // ---- stage 1: t = x @ w_x + b_x ; prelu ; l2norm -> xnT ----
        u64 a00, a01, a10, a11;
        {
            float bx0 = bxs[2 * jp], bx1 = bxs[2 * jp + 1];
            a00 = sp2(bx0); a01 = sp2(bx0);
            a10 = sp2(bx1); a11 = sp2(bx1);
            const float* xp = xT + rg * 4;
            const u64* wp = ((const u64*)w_s) + jp;
#pragma unroll 16
            for (int d = 0; d < DD; ++d) {
                float4 xq = *(const float4*)(xp + d * 20);
                float2 wf = upk2(wp[(size_t)d * 64]);
                u64 w0 = sp2(wf.x), w1 = sp2(wf.y);
                u64 x01 = pk2(xq.x, xq.y), x23 = pk2(xq.z, xq.w);
                fma2(a00, x01, w0); fma2(a01, x23, w0);
                fma2(a10, x01, w1); fma2(a11, x23, w1);
            }
        }
        float2 p00 = upk2(a00), p01 = upk2(a01), p10 = upk2(a10), p11 = upk2(a11);
        p00.x = prelu_f(p00.x, ax); p00.y = prelu_f(p00.y, ax);
        p01.x = prelu_f(p01.x, ax); p01.y = prelu_f(p01.y, ax);
        p10.x = prelu_f(p10.x, ax); p10.y = prelu_f(p10.y, ax);
        p11.x = prelu_f(p11.x, ax); p11.y = prelu_f(p11.y, ax);
        // per-row sum of squares (rows rg*4 + {0,1,2,3})
        float sq0 = p00.x * p00.x + p10.x * p10.x;
        float sq1 = p00.y * p00.y + p10.y * p10.y;
        float sq2 = p01.x * p01.x + p11.x * p11.x;
        float sq3 = p01.y * p01.y + p11.y * p11.y;
#pragma unroll
        for (int off = 16; off; off >>= 1) {
            sq0 += __shfl_xor_sync(~0u, sq0, off);
            sq1 += __shfl_xor_sync(~0u, sq1, off);
            sq2 += __shfl_xor_sync(~0u, sq2, off);
            sq3 += __shfl_xor_sync(~0u, sq3, off);
        }
        if (lane == 0) {
            red[warp * 4 + 0] = sq0; red[warp * 4 + 1] = sq1;
            red[warp * 4 + 2] = sq2; red[warp * 4 + 3] = sq3;
        }
        __syncthreads();
        if (t < TS) {
            int rgr = t >> 2, i = t & 3;
            float s = red[(2 * rgr) * 4 + i] + red[(2 * rgr + 1) * 4 + i];
            inv_s[t] = 1.0f / fmaxf(sqrtf(s), 1e-12f);
        }
        __syncthreads();
        {
            float i0 = inv_s[rg * 4 + 0], i1 = inv_s[rg * 4 + 1];
            float i2 = inv_s[rg * 4 + 2], i3 = inv_s[rg * 4 + 3];
            float* x0 = xnT + (2 * jp) * 20 + rg * 4;
            x0[0] = p00.x * i0; x0[1] = p00.y * i1; x0[2] = p01.x * i2; x0[3] = p01.y * i3;
            float* x1 = xnT + (2 * jp + 1) * 20 + rg * 4;
            x1[0] = p10.x * i0; x1[1] = p10.y * i1; x1[2] = p11.x * i2; x1[3] = p11.y * i3;
        }
        __syncthreads();

        // ---- stage 2: h1 = prelu(xh @ W_eff + c) ----
        if (t < 160) {
            int rg2 = t / 40;
            int rem = t - rg2 * 40;
            int h = rem / 20;
            int fp = rem - h * 20;  // f pair: cols 2fp, 2fp+1
            float c0 = c_s[h * FF + 2 * fp], c1 = c_s[h * FF + 2 * fp + 1];
            u64 b00 = sp2(c0), b01 = sp2(c0), b10 = sp2(c1), b11 = sp2(c1);
            const float* xp = xnT + (h * DD) * 20 + rg2 * 4;
            const u64* wp = ((const u64*)weff_s) + (size_t)h * (DD * FF / 2) + fp;
#pragma unroll 16
            for (int d = 0; d < DD; ++d) {
                float4 xq = *(const float4*)(xp + d * 20);
                float2 wf = upk2(wp[(size_t)d * (FF / 2)]);
                u64 w0 = sp2(wf.x), w1 = sp2(wf.y);
                u64 x01 = pk2(xq.x, xq.y), x23 = pk2(xq.z, xq.w);
                fma2(b00, x01, w0); fma2(b01, x23, w0);
                fma2(b10, x01, w1); fma2(b11, x23, w1);
            }
            float2 q00 = upk2(b00), q01 = upk2(b01), q10 = upk2(b10), q11 = upk2(b11);
            int rb = rg2 * 4;
            h1_s[((rb + 0) * 2 + h) * FF + 2 * fp] = prelu_f(q00.x, a1);
            h1_s[((rb + 1) * 2 + h) * FF + 2 * fp] = prelu_f(q00.y, a1);
            h1_s[((rb + 2) * 2 + h) * FF + 2 * fp] = prelu_f(q01.x, a1);
            h1_s[((rb + 3) * 2 + h) * FF + 2 * fp] = prelu_f(q01.y, a1);
            h1_s[((rb + 0) * 2 + h) * FF + 2 * fp + 1] = prelu_f(q10.x, a1);
            h1_s[((rb + 1) * 2 + h) * FF + 2 * fp + 1] = prelu_f(q10.y, a1);
            h1_s[((rb + 2) * 2 + h) * FF + 2 * fp + 1] = prelu_f(q11.x, a1);
            h1_s[((rb + 3) * 2 + h) * FF + 2 * fp + 1] = prelu_f(q11.y, a1);
        }
        __syncthreads();

        // ---- p = h1 @ w2 + b2 ----
        if (t < 32) {
            int rr = t >> 1, hh = t & 1;
            float acc = b2;
            const float* hp = h1_s + (rr * 2 + hh) * FF;
#pragma unroll
            for (int f = 0; f < FF; ++f) acc = fmaf(hp[f], w2_s[f], acc);
            p_s[rr * 2 + hh] = acc;
        }
        __syncthreads();

        // ---- accumulate out[h][d] += sum_r p[r][h] * xn[r][h*64+d] ----
        {
            int d = t & 63, h = (t >> 6) & 1, half = t >> 7;
            const float* xp = xnT + (h * DD + d) * 20 + half * 8;
            float4 xa = *(const float4*)(xp);
            float4 xb = *(const float4*)(xp + 4);
            int r0 = half * 8;
            racc += p_s[(r0 + 0) * 2 + h] * xa.x + p_s[(r0 + 1) * 2 + h] * xa.y
                  + p_s[(r0 + 2) * 2 + h] * xa.z + p_s[(r0 + 3) * 2 + h] * xa.w
                  + p_s[(r0 + 4) * 2 + h] * xb.x + p_s[(r0 + 5) * 2 + h] * xb.y
                  + p_s[(r0 + 6) * 2 + h] * xb.z + p_s[(r0 + 7) * 2 + h] * xb.w;
        }
        __syncthreads();
    }

    // ---- combine halves, write output ----
    accb[t] = racc;
    __syncthreads();
    if (t < HD) {
        out[(size_t)br * (BB * HD) + b * HD + t] = accb[t] + accb[t + HD];
    }
}

// ================= launcher ==============================================
extern "C" void kernel_launch(void* const* d_in, const int* in_sizes, int n_in,
                              void* d_out, int out_size) {
    const float* xl   = (const float*)d_in[0];
    const float* xn   = (const float*)d_in[1];
    const float* y    = (const float*)d_in[2];
    const float* uid  = (const float*)d_in[3];
    const float* osb  = (const float*)d_in[4];
    const float* zip  = (const float*)d_in[5];
    const float* w_ty = (const float*)d_in[6];
    const float* b_ty = (const float*)d_in[7];
    const float* a_ty = (const float*)d_in[8];
    const float* w_lx = (const float*)d_in[9];
    const float* b_lx = (const float*)d_in[10];
    const float* a_lx = (const float*)d_in[11];
    const float* w_nx = (const float*)d_in[12];
    const float* b_nx = (const float*)d_in[13];
    const float* a_nx = (const float*)d_in[14];
    const float* lw1  = (const float*)d_in[15];
    const float* lb1  = (const float*)d_in[16];
    const float* la1  = (const float*)d_in[17];
    const float* lw2  = (const float*)d_in[18];
    const float* lb2  = (const float*)d_in[19];
    const float* nw1  = (const float*)d_in[20];
    const float* nb1  = (const float*)d_in[21];
    const float* na1  = (const float*)d_in[22];
    const float* nw2  = (const float*)d_in[23];
    const float* nb2  = (const float*)d_in[24];
    float* out = (float*)d_out;

    cudaFuncSetAttribute(k_main, cudaFuncAttributeMaxDynamicSharedMemorySize, SM_BYTES);

    k_ytrans<<<BB, HD>>>(y, w_ty, b_ty, a_ty);
    k_weff<<<dim3(BB, 2, 2), 256>>>(lw1, lb1, nw1, nb1, uid, osb, zip);
    k_main<<<dim3(BB, 2), 256, SM_BYTES>>>(xl, xn,
                                           w_lx, b_lx, a_lx,
                                           w_nx, b_nx, a_nx,
                                           la1, na1, lw2, lb2, nw2, nb2,
                                           out);
}

// round 5
// speedup vs baseline: 3.7424x; 3.7424x over previous
#include <cuda_runtime.h>
#include <cuda_bf16.h>
#include <cstdint>

#define BB 256
#define SS 1024
#define DD 64
#define HD 128
#define FF 40

// ---------------- smem layout (byte offsets) ----------------
// bf16 rows of 64 K-elements padded to 144 bytes (conflict-free frag loads)
#define WSTR 144
#define OFF_WHI 0                  // 128 n x 144
#define OFF_WLO 18432
#define OFF_EHI 36864              // 80 n x 144 (Weff^T, 2 heads x 40)
#define OFF_ELO 48384
#define OFF_XHI 59904              // 64 rows x 144
#define OFF_XLO 69120
#define OFF_BX  78336              // 128 f32
#define OFF_C   78848              // 80 f32
#define OFF_W2  79168              // 40 f32
#define OFF_SQ  79328              // 128 f32 ([jh][64 rows])
#define OFF_RED 79840              // 8w x 4tig x 16 f32 = 2048
#define SMEM_TOTAL 81920

// ---------------- helpers ----------------
__device__ __forceinline__ float prelu_f(float x, float a) { return x >= 0.0f ? x : a * x; }
__device__ __forceinline__ float bfl(uint32_t u) { return __uint_as_float(u << 16); }
__device__ __forceinline__ float bfh(uint32_t u) { return __uint_as_float(u & 0xffff0000u); }

// pack (f0 -> low half, f1 -> high half)
__device__ __forceinline__ uint32_t pkbf(float f0, float f1) {
    uint32_t r;
    asm("cvt.rn.bf16x2.f32 %0, %1, %2;" : "=r"(r) : "f"(f1), "f"(f0));
    return r;
}
// split pair into bf16 hi + bf16 residual lo
__device__ __forceinline__ void split2(float f0, float f1, uint32_t& hi, uint32_t& lo) {
    uint32_t h = pkbf(f0, f1);
    lo = pkbf(f0 - bfl(h), f1 - bfh(h));
    hi = h;
}

__device__ __forceinline__ void mma_bf16(float* c, const uint32_t* a, const uint32_t* b) {
    asm volatile(
        "mma.sync.aligned.m16n8k16.row.col.f32.bf16.bf16.f32 "
        "{%0,%1,%2,%3}, {%4,%5,%6,%7}, {%8,%9}, {%0,%1,%2,%3};"
        : "+f"(c[0]), "+f"(c[1]), "+f"(c[2]), "+f"(c[3])
        : "r"(a[0]), "r"(a[1]), "r"(a[2]), "r"(a[3]), "r"(b[0]), "r"(b[1]));
}

// ---------------- device scratch ----------------
__device__ float g_ytrans[BB * HD];
__device__ float g_weff[2u * BB * 2 * DD * FF];
__device__ float g_c[2 * BB * 2 * FF];
__device__ float g_part[4][2 * BB * HD];

// ============ kernel 1: y_trans ============
__global__ void k_ytrans(const float* __restrict__ y, const float* __restrict__ w,
                         const float* __restrict__ bias, const float* __restrict__ a_) {
    int b = blockIdx.x;
    int j = threadIdx.x;  // 0..127
    float a = a_[0];
    __shared__ float ys[DD];
    __shared__ float red[4];
    if (j < DD) ys[j] = y[b * DD + j];
    __syncthreads();
    float acc = bias[j];
#pragma unroll
    for (int d = 0; d < DD; d++) acc = fmaf(ys[d], w[d * HD + j], acc);
    float t = prelu_f(acc, a);
    float sq = t * t;
#pragma unroll
    for (int off = 16; off; off >>= 1) sq += __shfl_xor_sync(~0u, sq, off);
    if ((j & 31) == 0) red[j >> 5] = sq;
    __syncthreads();
    float s = red[0] + red[1] + red[2] + red[3];
    float inv = 1.0f / fmaxf(sqrtf(s), 1e-12f);
    g_ytrans[b * HD + j] = t * inv;
}

// ============ kernel 2: W_eff and c ============
__global__ void k_weff(const float* __restrict__ lw1, const float* __restrict__ lb1,
                       const float* __restrict__ nw1, const float* __restrict__ nb1,
                       const float* __restrict__ uid, const float* __restrict__ osb,
                       const float* __restrict__ zip) {
    int b = blockIdx.x, h = blockIdx.y, br = blockIdx.z;
    const float* w1 = br ? nw1 : lw1;
    const float* b1 = br ? nb1 : lb1;
    __shared__ float yh[DD];
    __shared__ float side[56];
    int t = threadIdx.x;
    if (t < 64) {
        yh[t] = g_ytrans[b * HD + h * DD + t];
    } else if (t < 120) {
        int k = t - 64;
        side[k] = (k < 32) ? uid[b * 32 + k]
                : (k < 40) ? osb[b * 8 + (k - 32)]
                           : zip[b * 16 + (k - 40)];
    }
    __syncthreads();
    float* wout = g_weff + (((size_t)br * BB + b) * 2 + h) * (DD * FF);
    for (int i = t; i < DD * FF; i += 256) {
        int d = i / FF, f = i - d * FF;
        wout[i] = w1[d * FF + f] + w1[(128 + d) * FF + f] + yh[d] * w1[(64 + d) * FF + f];
    }
    if (t < FF) {
        float acc = b1[t];
#pragma unroll 8
        for (int d = 0; d < DD; d++)
            acc += yh[d] * (w1[(192 + d) * FF + t] - w1[(128 + d) * FF + t]);
#pragma unroll 8
        for (int k = 0; k < 56; k++) acc += side[k] * w1[(256 + k) * FF + t];
        g_c[(((size_t)br * BB + b) * 2 + h) * FF + t] = acc;
    }
}

// ============ kernel 3: main mma.sync kernel ============
__global__ __launch_bounds__(256, 2) void k_main(
    const float* __restrict__ xl, const float* __restrict__ xn_g,
    const float* __restrict__ wlx, const float* __restrict__ blx, const float* __restrict__ alx,
    const float* __restrict__ wnx, const float* __restrict__ bnx, const float* __restrict__ anx,
    const float* __restrict__ la1, const float* __restrict__ na1,
    const float* __restrict__ lw2, const float* __restrict__ lb2,
    const float* __restrict__ nw2, const float* __restrict__ nb2) {
    extern __shared__ char sm[];
    const int b = blockIdx.x, br = blockIdx.y, sh = blockIdx.z;
    const int t = threadIdx.x;
    const int w = t >> 5, lane = t & 31;
    const int mw = w & 3, jh = w >> 2;   // m-warp (rows mw*16..), n-half / head
    const int g = lane >> 2, tig = lane & 3;

    const float* xg = br ? xn_g : xl;
    const float* wx = br ? wnx : wlx;
    const float* bx = br ? bnx : blx;
    const float ax = br ? anx[0] : alx[0];
    const float a1 = br ? na1[0] : la1[0];
    const float* w2g = br ? nw2 : lw2;
    const float b2 = br ? nb2[0] : lb2[0];

    float* bxs  = (float*)(sm + OFF_BX);
    float* c_s  = (float*)(sm + OFF_C);
    float* w2_s = (float*)(sm + OFF_W2);
    float* sqf  = (float*)(sm + OFF_SQ);
    float* redf = (float*)(sm + OFF_RED);

    // ---- setup: transpose + bf16-split wx -> [j][d], Weff -> [h*40+f][d] ----
    for (int i = t; i < DD * HD; i += 256) {
        int d = i >> 7, j = i & 127;
        float v = wx[i];
        __nv_bfloat16 hv = __float2bfloat16(v);
        __nv_bfloat16 lv = __float2bfloat16(v - __bfloat162float(hv));
        *(__nv_bfloat16*)(sm + OFF_WHI + j * WSTR + d * 2) = hv;
        *(__nv_bfloat16*)(sm + OFF_WLO + j * WSTR + d * 2) = lv;
    }
    const float* wesrc = g_weff + ((size_t)br * BB + b) * 2 * (DD * FF);
    for (int i = t; i < 2 * DD * FF; i += 256) {
        int h_ = i / 2560;
        int rem = i - h_ * 2560;
        int d = rem / FF, f = rem - d * FF;
        float v = wesrc[i];
        __nv_bfloat16 hv = __float2bfloat16(v);
        __nv_bfloat16 lv = __float2bfloat16(v - __bfloat162float(hv));
        *(__nv_bfloat16*)(sm + OFF_EHI + (h_ * FF + f) * WSTR + d * 2) = hv;
        *(__nv_bfloat16*)(sm + OFF_ELO + (h_ * FF + f) * WSTR + d * 2) = lv;
    }
    {
        const float* csrc = g_c + ((size_t)br * BB + b) * 2 * FF;
        if (t < 128) bxs[t] = bx[t];
        else if (t < 208) c_s[t - 128] = csrc[t - 128];
        else if (t < 248) w2_s[t - 208] = w2g[t - 208];
    }
    __syncthreads();

    float racc[16];
#pragma unroll
    for (int i = 0; i < 16; i++) racc[i] = 0.0f;

    for (int tile = 0; tile < 4; ++tile) {
        const int s0 = sh * 256 + tile * 64;
        // ---- load x tile [64][64] fp32 -> split hi/lo bf16 smem ----
        const float4* xp = (const float4*)xg + (size_t)(b * SS + s0) * (DD / 4);
#pragma unroll
        for (int i = 0; i < 4; i++) {
            int idx = t + i * 256;          // 1024 float4
            int r = idx >> 4, kq = idx & 15;
            float4 v = xp[idx];
            uint32_t h01, l01, h23, l23;
            split2(v.x, v.y, h01, l01);
            split2(v.z, v.w, h23, l23);
            *(uint2*)(sm + OFF_XHI + r * WSTR + kq * 8) = make_uint2(h01, h23);
            *(uint2*)(sm + OFF_XLO + r * WSTR + kq * 8) = make_uint2(l01, l23);
        }
        __syncthreads();

        // ---- stage 1: t1 = x @ wx (64x128, K=64), 3x bf16 ----
        float acc[8][4];
#pragma unroll
        for (int nt = 0; nt < 8; nt++)
#pragma unroll
            for (int i = 0; i < 4; i++) acc[nt][i] = 0.0f;

#pragma unroll
        for (int kk = 0; kk < 4; kk++) {
            uint32_t aH[4], aL[4];
            const char* ab = sm + OFF_XHI + (mw * 16 + g) * WSTR + kk * 32 + tig * 4;
            aH[0] = *(const uint32_t*)(ab);
            aH[1] = *(const uint32_t*)(ab + 8 * WSTR);
            aH[2] = *(const uint32_t*)(ab + 16);
            aH[3] = *(const uint32_t*)(ab + 8 * WSTR + 16);
            aL[0] = *(const uint32_t*)(ab + 9216);
            aL[1] = *(const uint32_t*)(ab + 9216 + 8 * WSTR);
            aL[2] = *(const uint32_t*)(ab + 9216 + 16);
            aL[3] = *(const uint32_t*)(ab + 9216 + 8 * WSTR + 16);
#pragma unroll
            for (int nt = 0; nt < 8; nt++) {
                uint32_t bH[2], bL[2];
                const char* bb = sm + OFF_WHI + (jh * 64 + nt * 8 + g) * WSTR + kk * 32 + tig * 4;
                bH[0] = *(const uint32_t*)(bb);
                bH[1] = *(const uint32_t*)(bb + 16);
                bL[0] = *(const uint32_t*)(bb + 18432);
                bL[1] = *(const uint32_t*)(bb + 18432 + 16);
                mma_bf16(acc[nt], aH, bH);
                mma_bf16(acc[nt], aL, bH);
                mma_bf16(acc[nt], aH, bL);
            }
        }

        // ---- epilogue 1: bias + prelu + l2norm (in registers) ----
        float tvv[8][4];
        float s0r = 0.0f, s1r = 0.0f;
#pragma unroll
        for (int nt = 0; nt < 8; nt++) {
            int c0 = jh * 64 + nt * 8 + 2 * tig;
            float b0v = bxs[c0], b1v = bxs[c0 + 1];
            float t0 = prelu_f(acc[nt][0] + b0v, ax);
            float t1 = prelu_f(acc[nt][1] + b1v, ax);
            float t2 = prelu_f(acc[nt][2] + b0v, ax);
            float t3 = prelu_f(acc[nt][3] + b1v, ax);
            tvv[nt][0] = t0; tvv[nt][1] = t1; tvv[nt][2] = t2; tvv[nt][3] = t3;
            s0r += t0 * t0 + t1 * t1;
            s1r += t2 * t2 + t3 * t3;
        }
        s0r += __shfl_xor_sync(~0u, s0r, 1); s0r += __shfl_xor_sync(~0u, s0r, 2);
        s1r += __shfl_xor_sync(~0u, s1r, 1); s1r += __shfl_xor_sync(~0u, s1r, 2);
        int row0 = mw * 16 + g;
        if (tig == 0) {
            sqf[jh * 64 + row0] = s0r;
            sqf[jh * 64 + row0 + 8] = s1r;
        }
        __syncthreads();
        float inv0 = 1.0f / fmaxf(sqrtf(sqf[row0] + sqf[64 + row0]), 1e-12f);
        float inv1 = 1.0f / fmaxf(sqrtf(sqf[row0 + 8] + sqf[64 + row0 + 8]), 1e-12f);

        // normalize + build stage-2 A fragments (register resident)
        uint32_t a2h[4][4], a2l[4][4];
#pragma unroll
        for (int kk = 0; kk < 4; kk++) {
            split2(tvv[2 * kk][0] * inv0,     tvv[2 * kk][1] * inv0,     a2h[kk][0], a2l[kk][0]);
            split2(tvv[2 * kk][2] * inv1,     tvv[2 * kk][3] * inv1,     a2h[kk][1], a2l[kk][1]);
            split2(tvv[2 * kk + 1][0] * inv0, tvv[2 * kk + 1][1] * inv0, a2h[kk][2], a2l[kk][2]);
            split2(tvv[2 * kk + 1][2] * inv1, tvv[2 * kk + 1][3] * inv1, a2h[kk][3], a2l[kk][3]);
        }

        // ---- stage 2: h1 = xn_h @ Weff_h (64x40, K=64), 3x bf16 ----
        float acc2[5][4];
#pragma unroll
        for (int nt = 0; nt < 5; nt++)
#pragma unroll
            for (int i = 0; i < 4; i++) acc2[nt][i] = 0.0f;
#pragma unroll
        for (int kk = 0; kk < 4; kk++) {
#pragma unroll
            for (int nt = 0; nt < 5; nt++) {
                uint32_t bH[2], bL[2];
                const char* bb = sm + OFF_EHI + (jh * 40 + nt * 8 + g) * WSTR + kk * 32 + tig * 4;
                bH[0] = *(const uint32_t*)(bb);
                bH[1] = *(const uint32_t*)(bb + 16);
                bL[0] = *(const uint32_t*)(bb + 11520);
                bL[1] = *(const uint32_t*)(bb + 11520 + 16);
                mma_bf16(acc2[nt], a2h[kk], bH);
                mma_bf16(acc2[nt], a2l[kk], bH);
                mma_bf16(acc2[nt], a2h[kk], bL);
            }
        }

        // ---- epilogue 2: p = b2 + sum_f prelu(h1 + c) * w2 ----
        float p0 = 0.0f, p1 = 0.0f;
#pragma unroll
        for (int nt = 0; nt < 5; nt++) {
            int f0 = nt * 8 + 2 * tig;
            float c0v = c_s[jh * 40 + f0], c1v = c_s[jh * 40 + f0 + 1];
            float w0v = w2_s[f0], w1v = w2_s[f0 + 1];
            p0 += prelu_f(acc2[nt][0] + c0v, a1) * w0v + prelu_f(acc2[nt][1] + c1v, a1) * w1v;
            p1 += prelu_f(acc2[nt][2] + c0v, a1) * w0v + prelu_f(acc2[nt][3] + c1v, a1) * w1v;
        }
        p0 += __shfl_xor_sync(~0u, p0, 1); p0 += __shfl_xor_sync(~0u, p0, 2);
        p1 += __shfl_xor_sync(~0u, p1, 1); p1 += __shfl_xor_sync(~0u, p1, 2);
        p0 += b2; p1 += b2;

        // ---- epilogue 3: racc[col] += p0*xn[row g][col] + p1*xn[row g+8][col] ----
#pragma unroll
        for (int kk = 0; kk < 4; kk++) {
            float xa0 = bfl(a2h[kk][0]) + bfl(a2l[kk][0]);
            float xa1 = bfh(a2h[kk][0]) + bfh(a2l[kk][0]);
            float xb0 = bfl(a2h[kk][1]) + bfl(a2l[kk][1]);
            float xb1 = bfh(a2h[kk][1]) + bfh(a2l[kk][1]);
            racc[4 * kk + 0] += p0 * xa0 + p1 * xb0;
            racc[4 * kk + 1] += p0 * xa1 + p1 * xb1;
            float ya0 = bfl(a2h[kk][2]) + bfl(a2l[kk][2]);
            float ya1 = bfh(a2h[kk][2]) + bfh(a2l[kk][2]);
            float yb0 = bfl(a2h[kk][3]) + bfl(a2l[kk][3]);
            float yb1 = bfh(a2h[kk][3]) + bfh(a2l[kk][3]);
            racc[4 * kk + 2] += p0 * ya0 + p1 * yb0;
            racc[4 * kk + 3] += p0 * ya1 + p1 * yb1;
        }
        __syncthreads();  // protect x/sq smem for next tile
    }

    // ---- block reduction: sum over g-lanes, then over m-warps ----
#pragma unroll
    for (int i = 0; i < 16; i++) {
        racc[i] += __shfl_xor_sync(~0u, racc[i], 4);
        racc[i] += __shfl_xor_sync(~0u, racc[i], 8);
        racc[i] += __shfl_xor_sync(~0u, racc[i], 16);
    }
    if (lane < 4) {
#pragma unroll
        for (int i = 0; i < 16; i++) redf[(w * 4 + lane) * 16 + i] = racc[i];
    }
    __syncthreads();
    if (t < 128) {
        int col = t;
        int dl = col & 1;
        int tg = (col & 7) >> 1;
        int nt = (col & 63) >> 3;
        int jh2 = col >> 6;
        float v = 0.0f;
#pragma unroll
        for (int m2 = 0; m2 < 4; m2++)
            v += redf[((jh2 * 4 + m2) * 4 + tg) * 16 + nt * 2 + dl];
        g_part[sh][br * (BB * HD) + b * HD + col] = v;
    }
}

// ============ kernel 4: deterministic partial reduction ============
__global__ void k_reduce(float* __restrict__ out) {
    int i = blockIdx.x * 256 + threadIdx.x;
    out[i] = g_part[0][i] + g_part[1][i] + g_part[2][i] + g_part[3][i];
}

// ================= launcher ==============================================
extern "C" void kernel_launch(void* const* d_in, const int* in_sizes, int n_in,
                              void* d_out, int out_size) {
    const float* xl   = (const float*)d_in[0];
    const float* xn   = (const float*)d_in[1];
    const float* y    = (const float*)d_in[2];
    const float* uid  = (const float*)d_in[3];
    const float* osb  = (const float*)d_in[4];
    const float* zip  = (const float*)d_in[5];
    const float* w_ty = (const float*)d_in[6];
    const float* b_ty = (const float*)d_in[7];
    const float* a_ty = (const float*)d_in[8];
    const float* w_lx = (const float*)d_in[9];
    const float* b_lx = (const float*)d_in[10];
    const float* a_lx = (const float*)d_in[11];
    const float* w_nx = (const float*)d_in[12];
    const float* b_nx = (const float*)d_in[13];
    const float* a_nx = (const float*)d_in[14];
    const float* lw1  = (const float*)d_in[15];
    const float* lb1  = (const float*)d_in[16];
    const float* la1  = (const float*)d_in[17];
    const float* lw2  = (const float*)d_in[18];
    const float* lb2  = (const float*)d_in[19];
    const float* nw1  = (const float*)d_in[20];
    const float* nb1  = (const float*)d_in[21];
    const float* na1  = (const float*)d_in[22];
    const float* nw2  = (const float*)d_in[23];
    const float* nb2  = (const float*)d_in[24];
    float* out = (float*)d_out;

    cudaFuncSetAttribute(k_main, cudaFuncAttributeMaxDynamicSharedMemorySize, SMEM_TOTAL);

    k_ytrans<<<BB, HD>>>(y, w_ty, b_ty, a_ty);
    k_weff<<<dim3(BB, 2, 2), 256>>>(lw1, lb1, nw1, nb1, uid, osb, zip);
    k_main<<<dim3(BB, 2, 4), 256, SMEM_TOTAL>>>(xl, xn,
                                                w_lx, b_lx, a_lx,
                                                w_nx, b_nx, a_nx,
                                                la1, na1, lw2, lb2, nw2, nb2);
    k_reduce<<<(2 * BB * HD) / 256, 256>>>(out);
}

// round 6
// speedup vs baseline: 3.9410x; 1.0531x over previous
#include <cuda_runtime.h>
#include <cuda_bf16.h>
#include <cstdint>

#define BB 256
#define SS 1024
#define DD 64
#define HD 128
#define FF 40

// ---------------- smem layout (byte offsets) ----------------
// bf16 rows of 64 K-elements padded to 144 bytes (conflict-free frag loads)
#define WSTR 144
#define OFF_WHI 0                  // 128 n x 144
#define OFF_WLO 18432
#define OFF_EHI 36864              // 80 n x 144 (Weff^T, 2 heads x 40)
#define OFF_ELO 48384
#define OFF_XHI 59904              // 64 rows x 144
#define OFF_XLO 69120
#define OFF_BX  78336              // 128 f32
#define OFF_C   78848              // 80 f32
#define OFF_W2  79168              // 40 f32
#define OFF_SQ  79328              // 128 f32 ([jh][64 rows])
#define OFF_RED 79840              // 8w x 4tig x 16 f32 = 2048
#define SMEM_TOTAL 81920

// ---------------- helpers ----------------
__device__ __forceinline__ float prelu_f(float x, float a) { return x >= 0.0f ? x : a * x; }
__device__ __forceinline__ float bfl(uint32_t u) { return __uint_as_float(u << 16); }
__device__ __forceinline__ float bfh(uint32_t u) { return __uint_as_float(u & 0xffff0000u); }

__device__ __forceinline__ uint32_t smem_u32(const void* p) {
    uint32_t a;
    asm("{ .reg .u64 t; cvta.to.shared.u64 t, %1; cvt.u32.u64 %0, t; }" : "=r"(a) : "l"(p));
    return a;
}

// pack (f0 -> low half, f1 -> high half)
__device__ __forceinline__ uint32_t pkbf(float f0, float f1) {
    uint32_t r;
    asm("cvt.rn.bf16x2.f32 %0, %1, %2;" : "=r"(r) : "f"(f1), "f"(f0));
    return r;
}
// split pair into bf16 hi + bf16 residual lo
__device__ __forceinline__ void split2(float f0, float f1, uint32_t& hi, uint32_t& lo) {
    uint32_t h = pkbf(f0, f1);
    lo = pkbf(f0 - bfl(h), f1 - bfh(h));
    hi = h;
}

__device__ __forceinline__ void mma_bf16(float* c, const uint32_t* a, const uint32_t* b) {
    asm volatile(
        "mma.sync.aligned.m16n8k16.row.col.f32.bf16.bf16.f32 "
        "{%0,%1,%2,%3}, {%4,%5,%6,%7}, {%8,%9}, {%0,%1,%2,%3};"
        : "+f"(c[0]), "+f"(c[1]), "+f"(c[2]), "+f"(c[3])
        : "r"(a[0]), "r"(a[1]), "r"(a[2]), "r"(a[3]), "r"(b[0]), "r"(b[1]));
}

__device__ __forceinline__ void ldsm4(uint32_t* r, uint32_t addr) {
    asm volatile("ldmatrix.sync.aligned.m8n8.x4.shared.b16 {%0,%1,%2,%3}, [%4];"
        : "=r"(r[0]), "=r"(r[1]), "=r"(r[2]), "=r"(r[3]) : "r"(addr));
}
__device__ __forceinline__ void ldsm2(uint32_t* r, uint32_t addr) {
    asm volatile("ldmatrix.sync.aligned.m8n8.x2.shared.b16 {%0,%1}, [%2];"
        : "=r"(r[0]), "=r"(r[1]) : "r"(addr));
}

// ---------------- device scratch ----------------
__device__ float g_weff[2u * BB * 2 * DD * FF];
__device__ float g_c[2 * BB * 2 * FF];
__device__ float g_part[4][2 * BB * HD];

// ============ kernel 1: fused y_trans + W_eff + c ============
__global__ __launch_bounds__(256) void k_pre(
    const float* __restrict__ y, const float* __restrict__ w_ty,
    const float* __restrict__ b_ty, const float* __restrict__ a_ty,
    const float* __restrict__ uid, const float* __restrict__ osb,
    const float* __restrict__ zip,
    const float* __restrict__ lw1, const float* __restrict__ lb1,
    const float* __restrict__ nw1, const float* __restrict__ nb1) {
    int b = blockIdx.x, t = threadIdx.x;
    __shared__ float ys[DD], yt[HD], side[56], red[4];
    if (t < DD) ys[t] = y[b * DD + t];
    else if (t >= 64 && t < 120) {
        int k = t - 64;
        side[k] = (k < 32) ? uid[b * 32 + k]
                : (k < 40) ? osb[b * 8 + (k - 32)]
                           : zip[b * 16 + (k - 40)];
    }
    __syncthreads();
    float tv = 0.0f;
    if (t < HD) {
        float a = a_ty[0];
        float acc = b_ty[t];
#pragma unroll
        for (int d = 0; d < DD; d++) acc = fmaf(ys[d], w_ty[d * HD + t], acc);
        tv = prelu_f(acc, a);
        float sq = tv * tv;
#pragma unroll
        for (int off = 16; off; off >>= 1) sq += __shfl_xor_sync(~0u, sq, off);
        if ((t & 31) == 0) red[t >> 5] = sq;
    }
    __syncthreads();
    if (t < HD) {
        float s = red[0] + red[1] + red[2] + red[3];
        yt[t] = tv * (1.0f / fmaxf(sqrtf(s), 1e-12f));
    }
    __syncthreads();
#pragma unroll
    for (int br = 0; br < 2; br++) {
        const float* w1 = br ? nw1 : lw1;
        const float* b1 = br ? nb1 : lb1;
#pragma unroll
        for (int h = 0; h < 2; h++) {
            const float* yh = yt + h * DD;
            float* wout = g_weff + (((size_t)br * BB + b) * 2 + h) * (DD * FF);
            for (int i = t; i < DD * FF; i += 256) {
                int d = i / FF, f = i - d * FF;
                wout[i] = w1[d * FF + f] + w1[(128 + d) * FF + f] + yh[d] * w1[(64 + d) * FF + f];
            }
            if (t < FF) {
                float acc = b1[t];
#pragma unroll 8
                for (int d = 0; d < DD; d++)
                    acc += yh[d] * (w1[(192 + d) * FF + t] - w1[(128 + d) * FF + t]);
#pragma unroll 8
                for (int k = 0; k < 56; k++) acc += side[k] * w1[(256 + k) * FF + t];
                g_c[(((size_t)br * BB + b) * 2 + h) * FF + t] = acc;
            }
        }
    }
}

// ============ kernel 2: main mma.sync kernel ============
__global__ __launch_bounds__(256, 2) void k_main(
    const float* __restrict__ xl, const float* __restrict__ xn_g,
    const float* __restrict__ wlx, const float* __restrict__ blx, const float* __restrict__ alx,
    const float* __restrict__ wnx, const float* __restrict__ bnx, const float* __restrict__ anx,
    const float* __restrict__ la1, const float* __restrict__ na1,
    const float* __restrict__ lw2, const float* __restrict__ lb2,
    const float* __restrict__ nw2, const float* __restrict__ nb2) {
    extern __shared__ char sm[];
    const uint32_t sb = smem_u32(sm);
    const int b = blockIdx.x, br = blockIdx.y, sh = blockIdx.z;
    const int t = threadIdx.x;
    const int w = t >> 5, lane = t & 31;
    const int mw = w & 3, jh = w >> 2;   // m-warp (rows mw*16..), n-half / head
    const int g = lane >> 2, tig = lane & 3;

    const float* xg = br ? xn_g : xl;
    const float* wx = br ? wnx : wlx;
    const float* bx = br ? bnx : blx;
    const float ax = br ? anx[0] : alx[0];
    const float a1 = br ? na1[0] : la1[0];
    const float* w2g = br ? nw2 : lw2;
    const float b2 = br ? nb2[0] : lb2[0];

    float* bxs  = (float*)(sm + OFF_BX);
    float* c_s  = (float*)(sm + OFF_C);
    float* w2_s = (float*)(sm + OFF_W2);
    float* sqf  = (float*)(sm + OFF_SQ);
    float* redf = (float*)(sm + OFF_RED);

    // per-lane ldmatrix address components
    const uint32_t a_off = (uint32_t)(lane & 15) * WSTR + (uint32_t)(lane >> 4) * 16;
    const uint32_t b_off = (uint32_t)((lane >> 4) * 8 + (lane & 7)) * WSTR
                         + (uint32_t)((lane >> 3) & 1) * 16;
    const uint32_t b2_off = (uint32_t)(lane & 7) * WSTR + (uint32_t)((lane >> 3) & 1) * 16;

    // ---- setup: transpose + bf16-split wx -> [j][d], Weff -> [h*40+f][d] ----
    for (int i = t; i < DD * HD; i += 256) {
        int d = i >> 7, j = i & 127;
        float v = wx[i];
        __nv_bfloat16 hv = __float2bfloat16(v);
        __nv_bfloat16 lv = __float2bfloat16(v - __bfloat162float(hv));
        *(__nv_bfloat16*)(sm + OFF_WHI + j * WSTR + d * 2) = hv;
        *(__nv_bfloat16*)(sm + OFF_WLO + j * WSTR + d * 2) = lv;
    }
    const float* wesrc = g_weff + ((size_t)br * BB + b) * 2 * (DD * FF);
    for (int i = t; i < 2 * DD * FF; i += 256) {
        int h_ = i / 2560;
        int rem = i - h_ * 2560;
        int d = rem / FF, f = rem - d * FF;
        float v = wesrc[i];
        __nv_bfloat16 hv = __float2bfloat16(v);
        __nv_bfloat16 lv = __float2bfloat16(v - __bfloat162float(hv));
        *(__nv_bfloat16*)(sm + OFF_EHI + (h_ * FF + f) * WSTR + d * 2) = hv;
        *(__nv_bfloat16*)(sm + OFF_ELO + (h_ * FF + f) * WSTR + d * 2) = lv;
    }
    {
        const float* csrc = g_c + ((size_t)br * BB + b) * 2 * FF;
        if (t < 128) bxs[t] = bx[t];
        else if (t < 208) c_s[t - 128] = csrc[t - 128];
        else if (t < 248) w2_s[t - 208] = w2g[t - 208];
    }

    float racc[16];
#pragma unroll
    for (int i = 0; i < 16; i++) racc[i] = 0.0f;

    // prefetch tile 0
    const float4* xbase = (const float4*)xg + (size_t)(b * SS + sh * 256) * (DD / 4);
    float4 pf[4];
#pragma unroll
    for (int i = 0; i < 4; i++) pf[i] = xbase[t + i * 256];

    __syncthreads();

    for (int tile = 0; tile < 4; ++tile) {
        // ---- store prefetched x tile [64][64] -> split hi/lo bf16 smem ----
#pragma unroll
        for (int i = 0; i < 4; i++) {
            int idx = t + i * 256;          // 1024 float4
            int r = idx >> 4, kq = idx & 15;
            float4 v = pf[i];
            uint32_t h01, l01, h23, l23;
            split2(v.x, v.y, h01, l01);
            split2(v.z, v.w, h23, l23);
            *(uint2*)(sm + OFF_XHI + r * WSTR + kq * 8) = make_uint2(h01, h23);
            *(uint2*)(sm + OFF_XLO + r * WSTR + kq * 8) = make_uint2(l01, l23);
        }
        __syncthreads();

        // prefetch next tile (LDG latency overlaps stage-1 MMAs)
        if (tile < 3) {
            const float4* xp = xbase + (tile + 1) * 1024;
#pragma unroll
            for (int i = 0; i < 4; i++) pf[i] = xp[t + i * 256];
        }

        // ---- stage 1: t1 = x @ wx (64x128, K=64), 3x bf16 ----
        float acc[8][4];
#pragma unroll
        for (int nt = 0; nt < 8; nt++)
#pragma unroll
            for (int i = 0; i < 4; i++) acc[nt][i] = 0.0f;

#pragma unroll
        for (int kk = 0; kk < 4; kk++) {
            uint32_t aH[4], aL[4];
            uint32_t abase = sb + OFF_XHI + (uint32_t)(mw * 16) * WSTR + kk * 32 + a_off;
            ldsm4(aH, abase);
            ldsm4(aL, abase + (OFF_XLO - OFF_XHI));
#pragma unroll
            for (int np = 0; np < 4; np++) {
                uint32_t bH[4], bL[4];
                uint32_t bbase = sb + OFF_WHI + (uint32_t)(jh * 64 + np * 16) * WSTR + kk * 32 + b_off;
                ldsm4(bH, bbase);
                ldsm4(bL, bbase + (OFF_WLO - OFF_WHI));
                mma_bf16(acc[2 * np], aH, bH);
                mma_bf16(acc[2 * np], aL, bH);
                mma_bf16(acc[2 * np], aH, bL);
                mma_bf16(acc[2 * np + 1], aH, bH + 2);
                mma_bf16(acc[2 * np + 1], aL, bH + 2);
                mma_bf16(acc[2 * np + 1], aH, bL + 2);
            }
        }

        // ---- epilogue 1: bias + prelu + l2norm (in registers, acc reused) ----
        float s0r = 0.0f, s1r = 0.0f;
#pragma unroll
        for (int nt = 0; nt < 8; nt++) {
            int c0 = jh * 64 + nt * 8 + 2 * tig;
            float b0v = bxs[c0], b1v = bxs[c0 + 1];
            float t0 = prelu_f(acc[nt][0] + b0v, ax);
            float t1 = prelu_f(acc[nt][1] + b1v, ax);
            float t2 = prelu_f(acc[nt][2] + b0v, ax);
            float t3 = prelu_f(acc[nt][3] + b1v, ax);
            acc[nt][0] = t0; acc[nt][1] = t1; acc[nt][2] = t2; acc[nt][3] = t3;
            s0r += t0 * t0 + t1 * t1;
            s1r += t2 * t2 + t3 * t3;
        }
        s0r += __shfl_xor_sync(~0u, s0r, 1); s0r += __shfl_xor_sync(~0u, s0r, 2);
        s1r += __shfl_xor_sync(~0u, s1r, 1); s1r += __shfl_xor_sync(~0u, s1r, 2);
        int row0 = mw * 16 + g;
        if (tig == 0) {
            sqf[jh * 64 + row0] = s0r;
            sqf[jh * 64 + row0 + 8] = s1r;
        }
        __syncthreads();
        float inv0 = 1.0f / fmaxf(sqrtf(sqf[row0] + sqf[64 + row0]), 1e-12f);
        float inv1 = 1.0f / fmaxf(sqrtf(sqf[row0 + 8] + sqf[64 + row0 + 8]), 1e-12f);

        // normalize + build stage-2 A fragments (register resident)
        uint32_t a2h[4][4], a2l[4][4];
#pragma unroll
        for (int kk = 0; kk < 4; kk++) {
            split2(acc[2 * kk][0] * inv0,     acc[2 * kk][1] * inv0,     a2h[kk][0], a2l[kk][0]);
            split2(acc[2 * kk][2] * inv1,     acc[2 * kk][3] * inv1,     a2h[kk][1], a2l[kk][1]);
            split2(acc[2 * kk + 1][0] * inv0, acc[2 * kk + 1][1] * inv0, a2h[kk][2], a2l[kk][2]);
            split2(acc[2 * kk + 1][2] * inv1, acc[2 * kk + 1][3] * inv1, a2h[kk][3], a2l[kk][3]);
        }

        // ---- stage 2: h1 = xn_h @ Weff_h (64x40, K=64), 3x bf16 ----
        float acc2[5][4];
#pragma unroll
        for (int nt = 0; nt < 5; nt++)
#pragma unroll
            for (int i = 0; i < 4; i++) acc2[nt][i] = 0.0f;
#pragma unroll
        for (int kk = 0; kk < 4; kk++) {
#pragma unroll
            for (int np = 0; np < 2; np++) {
                uint32_t bH[4], bL[4];
                uint32_t bbase = sb + OFF_EHI + (uint32_t)(jh * 40 + np * 16) * WSTR + kk * 32 + b_off;
                ldsm4(bH, bbase);
                ldsm4(bL, bbase + (OFF_ELO - OFF_EHI));
                mma_bf16(acc2[2 * np], a2h[kk], bH);
                mma_bf16(acc2[2 * np], a2l[kk], bH);
                mma_bf16(acc2[2 * np], a2h[kk], bL);
                mma_bf16(acc2[2 * np + 1], a2h[kk], bH + 2);
                mma_bf16(acc2[2 * np + 1], a2l[kk], bH + 2);
                mma_bf16(acc2[2 * np + 1], a2h[kk], bL + 2);
            }
            {
                uint32_t bH[2], bL[2];
                uint32_t bbase = sb + OFF_EHI + (uint32_t)(jh * 40 + 32) * WSTR + kk * 32 + b2_off;
                ldsm2(bH, bbase);
                ldsm2(bL, bbase + (OFF_ELO - OFF_EHI));
                mma_bf16(acc2[4], a2h[kk], bH);
                mma_bf16(acc2[4], a2l[kk], bH);
                mma_bf16(acc2[4], a2h[kk], bL);
            }
        }

        // ---- epilogue 2: p = b2 + sum_f prelu(h1 + c) * w2 ----
        float p0 = 0.0f, p1 = 0.0f;
#pragma unroll
        for (int nt = 0; nt < 5; nt++) {
            int f0 = nt * 8 + 2 * tig;
            float c0v = c_s[jh * 40 + f0], c1v = c_s[jh * 40 + f0 + 1];
            float w0v = w2_s[f0], w1v = w2_s[f0 + 1];
            p0 += prelu_f(acc2[nt][0] + c0v, a1) * w0v + prelu_f(acc2[nt][1] + c1v, a1) * w1v;
            p1 += prelu_f(acc2[nt][2] + c0v, a1) * w0v + prelu_f(acc2[nt][3] + c1v, a1) * w1v;
        }
        p0 += __shfl_xor_sync(~0u, p0, 1); p0 += __shfl_xor_sync(~0u, p0, 2);
        p1 += __shfl_xor_sync(~0u, p1, 1); p1 += __shfl_xor_sync(~0u, p1, 2);
        p0 += b2; p1 += b2;

        // ---- epilogue 3: racc[col] += p0*xn[row g][col] + p1*xn[row g+8][col] ----
#pragma unroll
        for (int kk = 0; kk < 4; kk++) {
            float xa0 = bfl(a2h[kk][0]) + bfl(a2l[kk][0]);
            float xa1 = bfh(a2h[kk][0]) + bfh(a2l[kk][0]);
            float xb0 = bfl(a2h[kk][1]) + bfl(a2l[kk][1]);
            float xb1 = bfh(a2h[kk][1]) + bfh(a2l[kk][1]);
            racc[4 * kk + 0] += p0 * xa0 + p1 * xb0;
            racc[4 * kk + 1] += p0 * xa1 + p1 * xb1;
            float ya0 = bfl(a2h[kk][2]) + bfl(a2l[kk][2]);
            float ya1 = bfh(a2h[kk][2]) + bfh(a2l[kk][2]);
            float yb0 = bfl(a2h[kk][3]) + bfl(a2l[kk][3]);
            float yb1 = bfh(a2h[kk][3]) + bfh(a2l[kk][3]);
            racc[4 * kk + 2] += p0 * ya0 + p1 * yb0;
            racc[4 * kk + 3] += p0 * ya1 + p1 * yb1;
        }
        __syncthreads();  // protect x/sq smem for next tile
    }

    // ---- block reduction: sum over g-lanes, then over m-warps ----
#pragma unroll
    for (int i = 0; i < 16; i++) {
        racc[i] += __shfl_xor_sync(~0u, racc[i], 4);
        racc[i] += __shfl_xor_sync(~0u, racc[i], 8);
        racc[i] += __shfl_xor_sync(~0u, racc[i], 16);
    }
    if (lane < 4) {
#pragma unroll
        for (int i = 0; i < 16; i++) redf[(w * 4 + lane) * 16 + i] = racc[i];
    }
    __syncthreads();
    if (t < 128) {
        int col = t;
        int dl = col & 1;
        int tg = (col & 7) >> 1;
        int nt = (col & 63) >> 3;
        int jh2 = col >> 6;
        float v = 0.0f;
#pragma unroll
        for (int m2 = 0; m2 < 4; m2++)
            v += redf[((jh2 * 4 + m2) * 4 + tg) * 16 + nt * 2 + dl];
        g_part[sh][br * (BB * HD) + b * HD + col] = v;
    }
}

// ============ kernel 3: deterministic partial reduction (vectorized) ============
__global__ void k_reduce(float* __restrict__ out) {
    int i = blockIdx.x * 256 + threadIdx.x;  // 64 blocks x 256 thr x float4
    float4 a = ((const float4*)g_part[0])[i];
    float4 b = ((const float4*)g_part[1])[i];
    float4 c = ((const float4*)g_part[2])[i];
    float4 d = ((const float4*)g_part[3])[i];
    float4 s;
    s.x = (a.x + b.x) + (c.x + d.x);
    s.y = (a.y + b.y) + (c.y + d.y);
    s.z = (a.z + b.z) + (c.z + d.z);
    s.w = (a.w + b.w) + (c.w + d.w);
    ((float4*)out)[i] = s;
}

// ================= launcher ==============================================
extern "C" void kernel_launch(void* const* d_in, const int* in_sizes, int n_in,
                              void* d_out, int out_size) {
    const float* xl   = (const float*)d_in[0];
    const float* xn   = (const float*)d_in[1];
    const float* y    = (const float*)d_in[2];
    const float* uid  = (const float*)d_in[3];
    const float* osb  = (const float*)d_in[4];
    const float* zip  = (const float*)d_in[5];
    const float* w_ty = (const float*)d_in[6];
    const float* b_ty = (const float*)d_in[7];
    const float* a_ty = (const float*)d_in[8];
    const float* w_lx = (const float*)d_in[9];
    const float* b_lx = (const float*)d_in[10];
    const float* a_lx = (const float*)d_in[11];
    const float* w_nx = (const float*)d_in[12];
    const float* b_nx = (const float*)d_in[13];
    const float* a_nx = (const float*)d_in[14];
    const float* lw1  = (const float*)d_in[15];
    const float* lb1  = (const float*)d_in[16];
    const float* la1  = (const float*)d_in[17];
    const float* lw2  = (const float*)d_in[18];
    const float* lb2  = (const float*)d_in[19];
    const float* nw1  = (const float*)d_in[20];
    const float* nb1  = (const float*)d_in[21];
    const float* na1  = (const float*)d_in[22];
    const float* nw2  = (const float*)d_in[23];
    const float* nb2  = (const float*)d_in[24];
    float* out = (float*)d_out;

    cudaFuncSetAttribute(k_main, cudaFuncAttributeMaxDynamicSharedMemorySize, SMEM_TOTAL);

    k_pre<<<BB, 256>>>(y, w_ty, b_ty, a_ty, uid, osb, zip, lw1, lb1, nw1, nb1);
    k_main<<<dim3(BB, 2, 4), 256, SMEM_TOTAL>>>(xl, xn,
                                                w_lx, b_lx, a_lx,
                                                w_nx, b_nx, a_nx,
                                                la1, na1, lw2, lb2, nw2, nb2);
    k_reduce<<<(2 * BB * HD) / 1024, 256>>>(out);
}